// round 4
// baseline (speedup 1.0000x reference)
#include <cuda_runtime.h>
#include <cuda_bf16.h>
#include <math_constants.h>
#include <cstdint>

// Problem constants
#define B_SZ    2
#define N_SEQ   2048
#define DMODEL  2048
#define HQ      32
#define HKV     8
#define DHEAD   64
#define QKV_DIM 3072
#define TOKENS  4096
#define NH_NORM (HQ + HKV)

__device__ float g_qkv[(size_t)TOKENS * QKV_DIM];   // 48 MB
__device__ float g_y[(size_t)TOKENS * DMODEL];      // 32 MB

__device__ __forceinline__ uint32_t f2tf32(float f) {
    uint32_t u;
    asm("cvt.rna.tf32.f32 %0, %1;" : "=r"(u) : "f"(f));
    return u;
}

__device__ __forceinline__ void mma_tf32(float c[4], const uint32_t a[4],
                                         const uint32_t b[2]) {
    asm volatile(
        "mma.sync.aligned.m16n8k8.row.col.f32.tf32.tf32.f32 "
        "{%0,%1,%2,%3}, {%4,%5,%6,%7}, {%8,%9}, {%0,%1,%2,%3};\n"
        : "+f"(c[0]), "+f"(c[1]), "+f"(c[2]), "+f"(c[3])
        : "r"(a[0]), "r"(a[1]), "r"(a[2]), "r"(a[3]), "r"(b[0]), "r"(b[1]));
}

// ---------------------------------------------------------------------------
// TF32 GEMM: C[M,N] = A[M,K] * B[N,K]^T, 128x128 tile, BK=32, 8 warps.
// Double-buffered fragment-ordered smem; ONE barrier per K-step.
// ---------------------------------------------------------------------------
#define GEMM_SMEM_BYTES (2 * 8192 * 4)

__global__ __launch_bounds__(256) void gemm_tf32(const float* __restrict__ A,
                                                 const float* __restrict__ Bm,
                                                 float* __restrict__ C,
                                                 int M, int N, int K) {
    extern __shared__ uint32_t gsm[];
    uint32_t* Abuf[2] = {gsm, gsm + 8192};
    uint32_t* Bbuf[2] = {gsm + 4096, gsm + 12288};

    const int tid = threadIdx.x;
    const int lane = tid & 31, warp = tid >> 5;
    const int wm = warp >> 2, wn = warp & 3;
    const size_t bm = (size_t)blockIdx.y * 128, bn = (size_t)blockIdx.x * 128;

    int rowT[4], kqT[4];
#pragma unroll
    for (int s = 0; s < 4; s++) { int idx = tid + s * 256; rowT[s] = idx >> 3; kqT[s] = idx & 7; }

    const float* Abase = A + bm * K;
    const float* Bbase = Bm + bn * K;

    float4 ra[4], rb[4];
    float acc[4][4][4];
#pragma unroll
    for (int im = 0; im < 4; im++)
#pragma unroll
        for (int in = 0; in < 4; in++)
#pragma unroll
            for (int j = 0; j < 4; j++) acc[im][in][j] = 0.f;

#define LOADG(k0)                                                              \
    {                                                                          \
        _Pragma("unroll")                                                      \
        for (int s = 0; s < 4; s++) {                                          \
            ra[s] = *(const float4*)(Abase + (size_t)rowT[s] * K + (k0) + kqT[s] * 4); \
            rb[s] = *(const float4*)(Bbase + (size_t)rowT[s] * K + (k0) + kqT[s] * 4); \
        }                                                                      \
    }

#define STAGE(Af, Bf)                                                          \
    {                                                                          \
        _Pragma("unroll")                                                      \
        for (int s = 0; s < 4; s++) {                                          \
            int row = rowT[s];                                                 \
            int g = row & 7, ishi = (row >> 3) & 1, im = row >> 4;             \
            const float* pv = (const float*)&ra[s];                            \
            const float* pw = (const float*)&rb[s];                            \
            _Pragma("unroll")                                                  \
            for (int e = 0; e < 4; e++) {                                      \
                int col = kqT[s] * 4 + e;                                      \
                int t = col & 3, hk = (col >> 2) & 1, ik = col >> 3;           \
                int ln = g * 4 + t;                                            \
                (Af)[((im * 4 + ik) * 32 + ln) * 4 + (ishi + 2 * hk)] = f2tf32(pv[e]); \
                int inb = row >> 3, gb = row & 7;                              \
                (Bf)[((inb * 4 + ik) * 32 + gb * 4 + t) * 2 + hk] = f2tf32(pw[e]); \
            }                                                                  \
        }                                                                      \
    }

    LOADG(0);
    STAGE(Abuf[0], Bbuf[0]);
    __syncthreads();

    int cur = 0;
    for (int k0 = 32; k0 <= K; k0 += 32) {
        const bool more = (k0 < K);
        if (more) LOADG(k0);

        const uint32_t* Ac = Abuf[cur];
        const uint32_t* Bc = Bbuf[cur];

#pragma unroll
        for (int ik = 0; ik < 4; ik++) {
            uint4 af[4];
            uint32_t bf[4][2];
#pragma unroll
            for (int im = 0; im < 4; im++)
                af[im] = *(const uint4*)&Ac[(((wm * 4 + im) * 4 + ik) * 32 + lane) * 4];
#pragma unroll
            for (int in = 0; in < 4; in++) {
                uint2 tt = *(const uint2*)&Bc[(((wn * 4 + in) * 4 + ik) * 32 + lane) * 2];
                bf[in][0] = tt.x; bf[in][1] = tt.y;
            }
#pragma unroll
            for (int im = 0; im < 4; im++) {
                const uint32_t a4[4] = {af[im].x, af[im].y, af[im].z, af[im].w};
#pragma unroll
                for (int in = 0; in < 4; in++)
                    mma_tf32(acc[im][in], a4, bf[in]);
            }
        }

        if (more) STAGE(Abuf[cur ^ 1], Bbuf[cur ^ 1]);
        __syncthreads();
        cur ^= 1;
    }

#pragma unroll
    for (int im = 0; im < 4; im++) {
#pragma unroll
        for (int in = 0; in < 4; in++) {
            size_t r0 = bm + wm * 64 + im * 16 + (lane >> 2);
            size_t c0 = bn + wn * 32 + in * 8 + (lane & 3) * 2;
            *(float2*)&C[r0 * N + c0] = make_float2(acc[im][in][0], acc[im][in][1]);
            *(float2*)&C[(r0 + 8) * N + c0] = make_float2(acc[im][in][2], acc[im][in][3]);
        }
    }
#undef LOADG
#undef STAGE
}

// ---------------------------------------------------------------------------
// Fused per-head RMSNorm + RoPE (unchanged)
// ---------------------------------------------------------------------------
__global__ void norm_rope_kernel(const int* __restrict__ pos,
                                 const float* __restrict__ qw,
                                 const float* __restrict__ kw) {
    int gw = (blockIdx.x * blockDim.x + threadIdx.x) >> 5;
    int lane = threadIdx.x & 31;
    if (gw >= TOKENS * NH_NORM) return;
    int token = gw / NH_NORM;
    int h = gw - token * NH_NORM;
    int p = pos[token & (N_SEQ - 1)];

    float* ptr = g_qkv + (size_t)token * QKV_DIM + h * DHEAD;
    float x1 = ptr[lane];
    float x2 = ptr[lane + 32];
    float ss = x1 * x1 + x2 * x2;
#pragma unroll
    for (int o = 16; o; o >>= 1) ss += __shfl_xor_sync(0xffffffffu, ss, o);
    float r = rsqrtf(ss * (1.0f / 64.0f) + 1e-6f);
    const float* w = (h < HQ) ? qw : kw;
    x1 *= r * w[lane];
    x2 *= r * w[lane + 32];

    float inv = expf(-(float)(2 * lane) * (9.210340371976184f / 64.0f));
    float sv, cv;
    sincosf((float)p * inv, &sv, &cv);
    ptr[lane]      = x1 * cv - x2 * sv;
    ptr[lane + 32] = x1 * sv + x2 * cv;
}

// ---------------------------------------------------------------------------
// TF32 tensor-core causal GQA flash attention (double-buffered K/V).
// Br=128 (8 warps x 16 rows), Bc=64. ONE barrier per key block.
// ---------------------------------------------------------------------------
#define ATTN_SMEM_WORDS (8192 + 2 * 4096 + 2 * 4096 + 8192)
#define ATTN_SMEM_BYTES (ATTN_SMEM_WORDS * 4)

__global__ __launch_bounds__(256) void attn_mma() {
    extern __shared__ uint32_t smu[];
    uint32_t* Qfr = smu;                        // 8192
    uint32_t* Kbuf[2] = {smu + 8192, smu + 12288};
    uint32_t* Vbuf[2] = {smu + 16384, smu + 20480};
    uint32_t* Pfr = smu + 24576;                // 8192

    int qb = (gridDim.x - 1) - blockIdx.x;
    int h = blockIdx.y, b = blockIdx.z;
    int hk = h >> 2;
    int tid = threadIdx.x, lane = tid & 31, w = tid >> 5;
    int g = lane >> 2, t = lane & 3;
    size_t base = (size_t)b * N_SEQ;
    int q0 = qb * 128;

    // ---- stage Q tile (pre-scaled), fragment order + swizzle ----
#pragma unroll
    for (int s = 0; s < 8; s++) {
        int idx = tid + s * 256;
        int row = idx >> 4, f4 = idx & 15, d0 = f4 * 4;
        float4 v = *(const float4*)&g_qkv[(base + q0 + row) * QKV_DIM + h * DHEAD + d0];
        int wq = row >> 4, ishi = (row >> 3) & 1, gq = row & 7;
#pragma unroll
        for (int e = 0; e < 4; e++) {
            int d = d0 + e;
            int ik = d >> 3;
            int slot = (gq * 4 + (d & 3)) ^ ((ik & 3) * 4);
            Qfr[((wq * 8 + ik) * 32 + slot) * 4 + ishi + 2 * ((d >> 2) & 1)] =
                f2tf32(((const float*)&v)[e] * 0.125f);
        }
    }

    float4 rk[4], rv[4];
    const int nb = 2 * qb + 2;

#define LOADKV(kb_)                                                            \
    {                                                                          \
        int k0_ = (kb_) * 64;                                                  \
        _Pragma("unroll")                                                      \
        for (int s = 0; s < 4; s++) {                                          \
            int idx = tid + s * 256;                                           \
            int key = idx >> 4, f4 = idx & 15;                                 \
            size_t toff = (base + k0_ + key) * QKV_DIM;                        \
            rk[s] = *(const float4*)&g_qkv[toff + (HQ + hk) * DHEAD + f4 * 4]; \
            rv[s] = *(const float4*)&g_qkv[toff + (HQ + HKV + hk) * DHEAD + f4 * 4]; \
        }                                                                      \
    }

#define STAGEKV(Kf, Vf)                                                        \
    {                                                                          \
        _Pragma("unroll")                                                      \
        for (int s = 0; s < 4; s++) {                                          \
            int idx = tid + s * 256;                                           \
            int key = idx >> 4, f4 = idx & 15;                                 \
            _Pragma("unroll")                                                  \
            for (int e = 0; e < 4; e++) {                                      \
                int d = f4 * 4 + e;                                            \
                int ik = d >> 3, in = key >> 3;                                \
                int slK = ((key & 7) * 4 + (d & 3)) ^ ((ik & 3) * 4);          \
                (Kf)[((in * 8 + ik) * 32 + slK) * 2 + ((d >> 2) & 1)] =        \
                    f2tf32(((const float*)&rk[s])[e]);                         \
                int dt = d >> 3, ikk = key >> 3;                               \
                int slV = ((d & 7) * 4 + (key & 3)) ^ ((dt & 3) * 4);          \
                (Vf)[((ikk * 8 + dt) * 32 + slV) * 2 + ((key >> 2) & 1)] =     \
                    f2tf32(((const float*)&rv[s])[e]);                         \
            }                                                                  \
        }                                                                      \
    }

    float m0 = -CUDART_INF_F, m1 = -CUDART_INF_F, l0 = 0.f, l1 = 0.f;
    float o[8][4];
#pragma unroll
    for (int dt = 0; dt < 8; dt++)
#pragma unroll
        for (int j = 0; j < 4; j++) o[dt][j] = 0.f;

    uint32_t* Pw = Pfr + w * 1024;
    const int row0 = q0 + w * 16 + g;

    LOADKV(0);
    STAGEKV(Kbuf[0], Vbuf[0]);
    __syncthreads();

    int cur = 0;
    for (int kb = 0; kb < nb; kb++) {
        const bool more = (kb + 1 < nb);
        if (more) LOADKV(kb + 1);

        const uint32_t* Kc = Kbuf[cur];
        const uint32_t* Vc = Vbuf[cur];

        // ---- S = Q K^T ----
        float sacc[8][4];
#pragma unroll
        for (int n = 0; n < 8; n++)
#pragma unroll
            for (int j = 0; j < 4; j++) sacc[n][j] = 0.f;

#pragma unroll
        for (int ik = 0; ik < 8; ik++) {
            uint4 aq = *(const uint4*)&Qfr[((w * 8 + ik) * 32 + (lane ^ ((ik & 3) * 4))) * 4];
            const uint32_t a4[4] = {aq.x, aq.y, aq.z, aq.w};
#pragma unroll
            for (int n = 0; n < 8; n++) {
                uint2 bk = *(const uint2*)&Kc[((n * 8 + ik) * 32 + (lane ^ ((ik & 3) * 4))) * 2];
                const uint32_t b2[2] = {bk.x, bk.y};
                mma_tf32(sacc[n], a4, b2);
            }
        }

        // ---- causal mask ----
        if (kb >= 2 * qb) {
            int k0 = kb * 64;
#pragma unroll
            for (int n = 0; n < 8; n++) {
                int cb = k0 + n * 8 + 2 * t;
                if (cb > row0)     sacc[n][0] = -1e30f;
                if (cb + 1 > row0) sacc[n][1] = -1e30f;
                if (cb > row0 + 8)     sacc[n][2] = -1e30f;
                if (cb + 1 > row0 + 8) sacc[n][3] = -1e30f;
            }
        }

        // ---- online softmax ----
        float mx0 = -1e30f, mx1 = -1e30f;
#pragma unroll
        for (int n = 0; n < 8; n++) {
            mx0 = fmaxf(mx0, fmaxf(sacc[n][0], sacc[n][1]));
            mx1 = fmaxf(mx1, fmaxf(sacc[n][2], sacc[n][3]));
        }
        mx0 = fmaxf(mx0, __shfl_xor_sync(0xffffffffu, mx0, 1));
        mx0 = fmaxf(mx0, __shfl_xor_sync(0xffffffffu, mx0, 2));
        mx1 = fmaxf(mx1, __shfl_xor_sync(0xffffffffu, mx1, 1));
        mx1 = fmaxf(mx1, __shfl_xor_sync(0xffffffffu, mx1, 2));

        float mn0 = fmaxf(m0, mx0), mn1 = fmaxf(m1, mx1);
        float c0 = __expf(m0 - mn0), c1 = __expf(m1 - mn1);
        float s0 = 0.f, s1 = 0.f;
#pragma unroll
        for (int n = 0; n < 8; n++) {
            sacc[n][0] = __expf(sacc[n][0] - mn0);
            sacc[n][1] = __expf(sacc[n][1] - mn0);
            sacc[n][2] = __expf(sacc[n][2] - mn1);
            sacc[n][3] = __expf(sacc[n][3] - mn1);
            s0 += sacc[n][0] + sacc[n][1];
            s1 += sacc[n][2] + sacc[n][3];
        }
        s0 += __shfl_xor_sync(0xffffffffu, s0, 1);
        s0 += __shfl_xor_sync(0xffffffffu, s0, 2);
        s1 += __shfl_xor_sync(0xffffffffu, s1, 1);
        s1 += __shfl_xor_sync(0xffffffffu, s1, 2);
        l0 = l0 * c0 + s0; l1 = l1 * c1 + s1;
        m0 = mn0; m1 = mn1;
#pragma unroll
        for (int dt = 0; dt < 8; dt++) {
            o[dt][0] *= c0; o[dt][1] *= c0;
            o[dt][2] *= c1; o[dt][3] *= c1;
        }

        // ---- write P as A-fragments (per-warp private) ----
#pragma unroll
        for (int n = 0; n < 8; n++) {
            int ca = 2 * t, cb = 2 * t + 1;
            Pw[(n * 32 + g * 4 + (ca & 3)) * 4 + 0 + 2 * (ca >> 2)] = f2tf32(sacc[n][0]);
            Pw[(n * 32 + g * 4 + (cb & 3)) * 4 + 0 + 2 * (cb >> 2)] = f2tf32(sacc[n][1]);
            Pw[(n * 32 + g * 4 + (ca & 3)) * 4 + 1 + 2 * (ca >> 2)] = f2tf32(sacc[n][2]);
            Pw[(n * 32 + g * 4 + (cb & 3)) * 4 + 1 + 2 * (cb >> 2)] = f2tf32(sacc[n][3]);
        }
        __syncwarp();

        // ---- stage next K/V (overlaps with PV below across warps) ----
        if (more) STAGEKV(Kbuf[cur ^ 1], Vbuf[cur ^ 1]);

        // ---- O += P V ----
#pragma unroll
        for (int ik = 0; ik < 8; ik++) {
            uint4 ap = *(const uint4*)&Pw[(ik * 32 + lane) * 4];
            const uint32_t a4[4] = {ap.x, ap.y, ap.z, ap.w};
#pragma unroll
            for (int dt = 0; dt < 8; dt++) {
                uint2 bv = *(const uint2*)&Vc[((ik * 8 + dt) * 32 + (lane ^ ((dt & 3) * 4))) * 2];
                const uint32_t b2[2] = {bv.x, bv.y};
                mma_tf32(o[dt], a4, b2);
            }
        }

        __syncthreads();
        cur ^= 1;
    }

    // ---- epilogue ----
    float i0 = 1.f / l0, i1 = 1.f / l1;
#pragma unroll
    for (int dt = 0; dt < 8; dt++) {
        int col = h * DHEAD + dt * 8 + 2 * t;
        *(float2*)&g_y[(base + row0) * DMODEL + col] = make_float2(o[dt][0] * i0, o[dt][1] * i0);
        *(float2*)&g_y[(base + row0 + 8) * DMODEL + col] = make_float2(o[dt][2] * i1, o[dt][3] * i1);
    }
#undef LOADKV
#undef STAGEKV
}

// ---------------------------------------------------------------------------
// Launch
// ---------------------------------------------------------------------------
extern "C" void kernel_launch(void* const* d_in, const int* in_sizes, int n_in,
                              void* d_out, int out_size) {
    const float* x     = (const float*)d_in[0];
    const int*   pos   = (const int*)d_in[2];
    const float* qkv_w = (const float*)d_in[3];
    const float* out_w = (const float*)d_in[4];
    const float* qnw   = (const float*)d_in[5];
    const float* knw   = (const float*)d_in[6];
    float* out = (float*)d_out;

    float *qkv_buf, *y_buf;
    cudaGetSymbolAddress((void**)&qkv_buf, g_qkv);
    cudaGetSymbolAddress((void**)&y_buf, g_y);

    cudaFuncSetAttribute(gemm_tf32, cudaFuncAttributeMaxDynamicSharedMemorySize,
                         GEMM_SMEM_BYTES);
    cudaFuncSetAttribute(attn_mma, cudaFuncAttributeMaxDynamicSharedMemorySize,
                         ATTN_SMEM_BYTES);

    gemm_tf32<<<dim3(QKV_DIM / 128, TOKENS / 128), 256, GEMM_SMEM_BYTES>>>(
        x, qkv_w, qkv_buf, TOKENS, QKV_DIM, DMODEL);
    {
        int warps = TOKENS * NH_NORM;
        int threads = warps * 32;
        norm_rope_kernel<<<(threads + 255) / 256, 256>>>(pos, qnw, knw);
    }
    attn_mma<<<dim3(N_SEQ / 128, HQ, B_SZ), 256, ATTN_SMEM_BYTES>>>();
    gemm_tf32<<<dim3(DMODEL / 128, TOKENS / 128), 256, GEMM_SMEM_BYTES>>>(
        y_buf, out_w, out, TOKENS, DMODEL, DMODEL);
}

// round 5
// speedup vs baseline: 1.0928x; 1.0928x over previous
#include <cuda_runtime.h>
#include <cuda_bf16.h>
#include <math_constants.h>
#include <cstdint>

// Problem constants
#define B_SZ    2
#define N_SEQ   2048
#define DMODEL  2048
#define HQ      32
#define HKV     8
#define DHEAD   64
#define QKV_DIM 3072
#define TOKENS  4096
#define NH_NORM (HQ + HKV)

__device__ float g_qkv[(size_t)TOKENS * QKV_DIM];   // 48 MB
__device__ float g_y[(size_t)TOKENS * DMODEL];      // 32 MB

__device__ __forceinline__ uint32_t f2tf32(float f) {
    uint32_t u;
    asm("cvt.rna.tf32.f32 %0, %1;" : "=r"(u) : "f"(f));
    return u;
}

__device__ __forceinline__ void mma_tf32(float c[4], const uint32_t a[4],
                                         const uint32_t b[2]) {
    asm volatile(
        "mma.sync.aligned.m16n8k8.row.col.f32.tf32.tf32.f32 "
        "{%0,%1,%2,%3}, {%4,%5,%6,%7}, {%8,%9}, {%0,%1,%2,%3};\n"
        : "+f"(c[0]), "+f"(c[1]), "+f"(c[2]), "+f"(c[3])
        : "r"(a[0]), "r"(a[1]), "r"(a[2]), "r"(a[3]), "r"(b[0]), "r"(b[1]));
}

// ---------------------------------------------------------------------------
// TF32 GEMM: C[M,N] = A[M,K] * B[N,K]^T.
// 128x64 CTA tile, BK=32, 8 warps (4x2), warp tile 32x32, acc=32 regs
// -> 2 CTAs/SM (16 warps). Fragment-ordered static smem, single buffer.
// ---------------------------------------------------------------------------
__global__ __launch_bounds__(256, 2) void gemm_tf32(const float* __restrict__ A,
                                                    const float* __restrict__ Bm,
                                                    float* __restrict__ C,
                                                    int M, int N, int K) {
    __shared__ uint32_t Afr[4096];   // 8 m16-tiles x 4 ik x 32 lanes x 4 regs
    __shared__ uint32_t Bfr[2048];   // 8 n8-tiles  x 4 ik x 32 lanes x 2 regs

    const int tid = threadIdx.x;
    const int lane = tid & 31, warp = tid >> 5;
    const int wm = warp >> 1, wn = warp & 1;   // 4 x 2 warps
    const size_t bm = (size_t)blockIdx.y * 128, bn = (size_t)blockIdx.x * 64;

    const float* Abase = A + bm * K;
    const float* Bbase = Bm + bn * K;

    float4 ra[4], rb[2];
    float acc[2][4][4];
#pragma unroll
    for (int im = 0; im < 2; im++)
#pragma unroll
        for (int in = 0; in < 4; in++)
#pragma unroll
            for (int j = 0; j < 4; j++) acc[im][in][j] = 0.f;

#define LOADG(k0)                                                              \
    {                                                                          \
        _Pragma("unroll")                                                      \
        for (int s = 0; s < 4; s++) {                                          \
            int idx = tid + s * 256;                                           \
            ra[s] = *(const float4*)(Abase + (size_t)(idx >> 3) * K + (k0) + (idx & 7) * 4); \
        }                                                                      \
        _Pragma("unroll")                                                      \
        for (int s = 0; s < 2; s++) {                                          \
            int idx = tid + s * 256;                                           \
            rb[s] = *(const float4*)(Bbase + (size_t)(idx >> 3) * K + (k0) + (idx & 7) * 4); \
        }                                                                      \
    }

#define STAGE()                                                                \
    {                                                                          \
        _Pragma("unroll")                                                      \
        for (int s = 0; s < 4; s++) {                                          \
            int idx = tid + s * 256;                                           \
            int row = idx >> 3, kq = idx & 7;                                  \
            int g = row & 7, ishi = (row >> 3) & 1, im = row >> 4;             \
            const float* pv = (const float*)&ra[s];                            \
            _Pragma("unroll")                                                  \
            for (int e = 0; e < 4; e++) {                                      \
                int col = kq * 4 + e;                                          \
                int t = col & 3, hk = (col >> 2) & 1, ik = col >> 3;           \
                Afr[((im * 4 + ik) * 32 + g * 4 + t) * 4 + (ishi + 2 * hk)] = f2tf32(pv[e]); \
            }                                                                  \
        }                                                                      \
        _Pragma("unroll")                                                      \
        for (int s = 0; s < 2; s++) {                                          \
            int idx = tid + s * 256;                                           \
            int row = idx >> 3, kq = idx & 7;                                  \
            int inb = row >> 3, gb = row & 7;                                  \
            const float* pw = (const float*)&rb[s];                            \
            _Pragma("unroll")                                                  \
            for (int e = 0; e < 4; e++) {                                      \
                int col = kq * 4 + e;                                          \
                int t = col & 3, hk = (col >> 2) & 1, ik = col >> 3;           \
                Bfr[((inb * 4 + ik) * 32 + gb * 4 + t) * 2 + hk] = f2tf32(pw[e]); \
            }                                                                  \
        }                                                                      \
    }

    LOADG(0);
    STAGE();
    __syncthreads();

    for (int k0 = 32; k0 <= K; k0 += 32) {
        const bool more = (k0 < K);
        if (more) LOADG(k0);

#pragma unroll
        for (int ik = 0; ik < 4; ik++) {
            uint4 af[2];
            uint32_t bf[4][2];
#pragma unroll
            for (int im = 0; im < 2; im++)
                af[im] = *(const uint4*)&Afr[(((wm * 2 + im) * 4 + ik) * 32 + lane) * 4];
#pragma unroll
            for (int in = 0; in < 4; in++) {
                uint2 tt = *(const uint2*)&Bfr[(((wn * 4 + in) * 4 + ik) * 32 + lane) * 2];
                bf[in][0] = tt.x; bf[in][1] = tt.y;
            }
#pragma unroll
            for (int im = 0; im < 2; im++) {
                const uint32_t a4[4] = {af[im].x, af[im].y, af[im].z, af[im].w};
#pragma unroll
                for (int in = 0; in < 4; in++)
                    mma_tf32(acc[im][in], a4, bf[in]);
            }
        }
        __syncthreads();
        if (more) {
            STAGE();
            __syncthreads();
        }
    }

#pragma unroll
    for (int im = 0; im < 2; im++) {
#pragma unroll
        for (int in = 0; in < 4; in++) {
            size_t r0 = bm + wm * 32 + im * 16 + (lane >> 2);
            size_t c0 = bn + wn * 32 + in * 8 + (lane & 3) * 2;
            *(float2*)&C[r0 * N + c0] = make_float2(acc[im][in][0], acc[im][in][1]);
            *(float2*)&C[(r0 + 8) * N + c0] = make_float2(acc[im][in][2], acc[im][in][3]);
        }
    }
#undef LOADG
#undef STAGE
}

// ---------------------------------------------------------------------------
// Fused per-head RMSNorm + RoPE (unchanged)
// ---------------------------------------------------------------------------
__global__ void norm_rope_kernel(const int* __restrict__ pos,
                                 const float* __restrict__ qw,
                                 const float* __restrict__ kw) {
    int gw = (blockIdx.x * blockDim.x + threadIdx.x) >> 5;
    int lane = threadIdx.x & 31;
    if (gw >= TOKENS * NH_NORM) return;
    int token = gw / NH_NORM;
    int h = gw - token * NH_NORM;
    int p = pos[token & (N_SEQ - 1)];

    float* ptr = g_qkv + (size_t)token * QKV_DIM + h * DHEAD;
    float x1 = ptr[lane];
    float x2 = ptr[lane + 32];
    float ss = x1 * x1 + x2 * x2;
#pragma unroll
    for (int o = 16; o; o >>= 1) ss += __shfl_xor_sync(0xffffffffu, ss, o);
    float r = rsqrtf(ss * (1.0f / 64.0f) + 1e-6f);
    const float* w = (h < HQ) ? qw : kw;
    x1 *= r * w[lane];
    x2 *= r * w[lane + 32];

    float inv = expf(-(float)(2 * lane) * (9.210340371976184f / 64.0f));
    float sv, cv;
    sincosf((float)p * inv, &sv, &cv);
    ptr[lane]      = x1 * cv - x2 * sv;
    ptr[lane + 32] = x1 * sv + x2 * cv;
}

// ---------------------------------------------------------------------------
// TF32 tensor-core causal GQA flash attention (exact R3 version, 1712us run).
// ---------------------------------------------------------------------------
#define ATTN_SMEM_WORDS (8192 + 4096 + 4096 + 8192)
#define ATTN_SMEM_BYTES (ATTN_SMEM_WORDS * 4)

__global__ __launch_bounds__(256) void attn_mma() {
    extern __shared__ uint32_t smu[];
    uint32_t* Qfr = smu;             // 8192
    uint32_t* Kfr = smu + 8192;      // 4096
    uint32_t* Vfr = smu + 12288;     // 4096
    uint32_t* Pfr = smu + 16384;     // 8192

    int qb = (gridDim.x - 1) - blockIdx.x;
    int h = blockIdx.y, b = blockIdx.z;
    int hk = h >> 2;
    int tid = threadIdx.x, lane = tid & 31, w = tid >> 5;
    int g = lane >> 2, t = lane & 3;
    size_t base = (size_t)b * N_SEQ;
    int q0 = qb * 128;

#pragma unroll
    for (int s = 0; s < 8; s++) {
        int idx = tid + s * 256;
        int row = idx >> 4, f4 = idx & 15, d0 = f4 * 4;
        float4 v = *(const float4*)&g_qkv[(base + q0 + row) * QKV_DIM + h * DHEAD + d0];
        int wq = row >> 4, ishi = (row >> 3) & 1, gq = row & 7;
#pragma unroll
        for (int e = 0; e < 4; e++) {
            int d = d0 + e;
            int ik = d >> 3;
            int slot = (gq * 4 + (d & 3)) ^ ((ik & 3) * 4);
            Qfr[((wq * 8 + ik) * 32 + slot) * 4 + ishi + 2 * ((d >> 2) & 1)] =
                f2tf32(((const float*)&v)[e] * 0.125f);
        }
    }

    float4 rk[4], rv[4];
    const int nb = 2 * qb + 2;

#define LOADKV(kb_)                                                            \
    {                                                                          \
        int k0_ = (kb_) * 64;                                                  \
        _Pragma("unroll")                                                      \
        for (int s = 0; s < 4; s++) {                                          \
            int idx = tid + s * 256;                                           \
            int key = idx >> 4, f4 = idx & 15;                                 \
            size_t toff = (base + k0_ + key) * QKV_DIM;                        \
            rk[s] = *(const float4*)&g_qkv[toff + (HQ + hk) * DHEAD + f4 * 4]; \
            rv[s] = *(const float4*)&g_qkv[toff + (HQ + HKV + hk) * DHEAD + f4 * 4]; \
        }                                                                      \
    }

#define STAGEKV()                                                              \
    {                                                                          \
        _Pragma("unroll")                                                      \
        for (int s = 0; s < 4; s++) {                                          \
            int idx = tid + s * 256;                                           \
            int key = idx >> 4, f4 = idx & 15;                                 \
            _Pragma("unroll")                                                  \
            for (int e = 0; e < 4; e++) {                                      \
                int d = f4 * 4 + e;                                            \
                int ik = d >> 3, in = key >> 3;                                \
                int slK = ((key & 7) * 4 + (d & 3)) ^ ((ik & 3) * 4);          \
                Kfr[((in * 8 + ik) * 32 + slK) * 2 + ((d >> 2) & 1)] =         \
                    f2tf32(((const float*)&rk[s])[e]);                         \
                int dt = d >> 3, ikk = key >> 3;                               \
                int slV = ((d & 7) * 4 + (key & 3)) ^ ((dt & 3) * 4);          \
                Vfr[((ikk * 8 + dt) * 32 + slV) * 2 + ((key >> 2) & 1)] =      \
                    f2tf32(((const float*)&rv[s])[e]);                         \
            }                                                                  \
        }                                                                      \
    }

    float m0 = -CUDART_INF_F, m1 = -CUDART_INF_F, l0 = 0.f, l1 = 0.f;
    float o[8][4];
#pragma unroll
    for (int dt = 0; dt < 8; dt++)
#pragma unroll
        for (int j = 0; j < 4; j++) o[dt][j] = 0.f;

    uint32_t* Pw = Pfr + w * 1024;
    const int row0 = q0 + w * 16 + g;

    LOADKV(0);

    for (int kb = 0; kb < nb; kb++) {
        if (kb > 0) __syncthreads();
        STAGEKV();
        __syncthreads();
        if (kb + 1 < nb) LOADKV(kb + 1);

        float sacc[8][4];
#pragma unroll
        for (int n = 0; n < 8; n++)
#pragma unroll
            for (int j = 0; j < 4; j++) sacc[n][j] = 0.f;

#pragma unroll
        for (int ik = 0; ik < 8; ik++) {
            uint4 aq = *(const uint4*)&Qfr[((w * 8 + ik) * 32 + (lane ^ ((ik & 3) * 4))) * 4];
            const uint32_t a4[4] = {aq.x, aq.y, aq.z, aq.w};
#pragma unroll
            for (int n = 0; n < 8; n++) {
                uint2 bk = *(const uint2*)&Kfr[((n * 8 + ik) * 32 + (lane ^ ((ik & 3) * 4))) * 2];
                const uint32_t b2[2] = {bk.x, bk.y};
                mma_tf32(sacc[n], a4, b2);
            }
        }

        if (kb >= 2 * qb) {
            int k0 = kb * 64;
#pragma unroll
            for (int n = 0; n < 8; n++) {
                int cb = k0 + n * 8 + 2 * t;
                if (cb > row0)     sacc[n][0] = -1e30f;
                if (cb + 1 > row0) sacc[n][1] = -1e30f;
                if (cb > row0 + 8)     sacc[n][2] = -1e30f;
                if (cb + 1 > row0 + 8) sacc[n][3] = -1e30f;
            }
        }

        float mx0 = -1e30f, mx1 = -1e30f;
#pragma unroll
        for (int n = 0; n < 8; n++) {
            mx0 = fmaxf(mx0, fmaxf(sacc[n][0], sacc[n][1]));
            mx1 = fmaxf(mx1, fmaxf(sacc[n][2], sacc[n][3]));
        }
        mx0 = fmaxf(mx0, __shfl_xor_sync(0xffffffffu, mx0, 1));
        mx0 = fmaxf(mx0, __shfl_xor_sync(0xffffffffu, mx0, 2));
        mx1 = fmaxf(mx1, __shfl_xor_sync(0xffffffffu, mx1, 1));
        mx1 = fmaxf(mx1, __shfl_xor_sync(0xffffffffu, mx1, 2));

        float mn0 = fmaxf(m0, mx0), mn1 = fmaxf(m1, mx1);
        float c0 = __expf(m0 - mn0), c1 = __expf(m1 - mn1);
        float s0 = 0.f, s1 = 0.f;
#pragma unroll
        for (int n = 0; n < 8; n++) {
            sacc[n][0] = __expf(sacc[n][0] - mn0);
            sacc[n][1] = __expf(sacc[n][1] - mn0);
            sacc[n][2] = __expf(sacc[n][2] - mn1);
            sacc[n][3] = __expf(sacc[n][3] - mn1);
            s0 += sacc[n][0] + sacc[n][1];
            s1 += sacc[n][2] + sacc[n][3];
        }
        s0 += __shfl_xor_sync(0xffffffffu, s0, 1);
        s0 += __shfl_xor_sync(0xffffffffu, s0, 2);
        s1 += __shfl_xor_sync(0xffffffffu, s1, 1);
        s1 += __shfl_xor_sync(0xffffffffu, s1, 2);
        l0 = l0 * c0 + s0; l1 = l1 * c1 + s1;
        m0 = mn0; m1 = mn1;
#pragma unroll
        for (int dt = 0; dt < 8; dt++) {
            o[dt][0] *= c0; o[dt][1] *= c0;
            o[dt][2] *= c1; o[dt][3] *= c1;
        }

#pragma unroll
        for (int n = 0; n < 8; n++) {
            int ca = 2 * t, cb = 2 * t + 1;
            Pw[(n * 32 + g * 4 + (ca & 3)) * 4 + 0 + 2 * (ca >> 2)] = f2tf32(sacc[n][0]);
            Pw[(n * 32 + g * 4 + (cb & 3)) * 4 + 0 + 2 * (cb >> 2)] = f2tf32(sacc[n][1]);
            Pw[(n * 32 + g * 4 + (ca & 3)) * 4 + 1 + 2 * (ca >> 2)] = f2tf32(sacc[n][2]);
            Pw[(n * 32 + g * 4 + (cb & 3)) * 4 + 1 + 2 * (cb >> 2)] = f2tf32(sacc[n][3]);
        }
        __syncwarp();

#pragma unroll
        for (int ik = 0; ik < 8; ik++) {
            uint4 ap = *(const uint4*)&Pw[(ik * 32 + lane) * 4];
            const uint32_t a4[4] = {ap.x, ap.y, ap.z, ap.w};
#pragma unroll
            for (int dt = 0; dt < 8; dt++) {
                uint2 bv = *(const uint2*)&Vfr[((ik * 8 + dt) * 32 + (lane ^ ((dt & 3) * 4))) * 2];
                const uint32_t b2[2] = {bv.x, bv.y};
                mma_tf32(o[dt], a4, b2);
            }
        }
    }

    float i0 = 1.f / l0, i1 = 1.f / l1;
#pragma unroll
    for (int dt = 0; dt < 8; dt++) {
        int col = h * DHEAD + dt * 8 + 2 * t;
        *(float2*)&g_y[(base + row0) * DMODEL + col] = make_float2(o[dt][0] * i0, o[dt][1] * i0);
        *(float2*)&g_y[(base + row0 + 8) * DMODEL + col] = make_float2(o[dt][2] * i1, o[dt][3] * i1);
    }
#undef LOADKV
#undef STAGEKV
}

// ---------------------------------------------------------------------------
// Launch
// ---------------------------------------------------------------------------
extern "C" void kernel_launch(void* const* d_in, const int* in_sizes, int n_in,
                              void* d_out, int out_size) {
    const float* x     = (const float*)d_in[0];
    const int*   pos   = (const int*)d_in[2];
    const float* qkv_w = (const float*)d_in[3];
    const float* out_w = (const float*)d_in[4];
    const float* qnw   = (const float*)d_in[5];
    const float* knw   = (const float*)d_in[6];
    float* out = (float*)d_out;

    float *qkv_buf, *y_buf;
    cudaGetSymbolAddress((void**)&qkv_buf, g_qkv);
    cudaGetSymbolAddress((void**)&y_buf, g_y);

    gemm_tf32<<<dim3(QKV_DIM / 64, TOKENS / 128), 256>>>(x, qkv_w, qkv_buf,
                                                         TOKENS, QKV_DIM, DMODEL);
    {
        int warps = TOKENS * NH_NORM;
        int threads = warps * 32;
        norm_rope_kernel<<<(threads + 255) / 256, 256>>>(pos, qnw, knw);
    }
    cudaFuncSetAttribute(attn_mma, cudaFuncAttributeMaxDynamicSharedMemorySize,
                         ATTN_SMEM_BYTES);
    attn_mma<<<dim3(N_SEQ / 128, HQ, B_SZ), 256, ATTN_SMEM_BYTES>>>();
    gemm_tf32<<<dim3(DMODEL / 64, TOKENS / 128), 256>>>(y_buf, out_w, out,
                                                        TOKENS, DMODEL, DMODEL);
}

// round 8
// speedup vs baseline: 2.2697x; 2.0768x over previous
#include <cuda_runtime.h>
#include <cuda_fp16.h>
#include <math_constants.h>
#include <cstdint>

// Problem constants
#define B_SZ    2
#define N_SEQ   2048
#define DMODEL  2048
#define HQ      32
#define HKV     8
#define DHEAD   64
#define QKV_DIM 3072
#define TOKENS  4096
#define NH_NORM (HQ + HKV)

__device__ float g_qkv[(size_t)TOKENS * QKV_DIM];   // 48 MB
__device__ float g_y[(size_t)TOKENS * DMODEL];      // 32 MB

__device__ __forceinline__ uint32_t packh2(float a, float b) {
    __half2 h = __floats2half2_rn(a, b);
    return *(uint32_t*)&h;
}

__device__ __forceinline__ void mma_f16(float c[4], const uint32_t a[4],
                                        const uint32_t b[2]) {
    asm volatile(
        "mma.sync.aligned.m16n8k16.row.col.f32.f16.f16.f32 "
        "{%0,%1,%2,%3}, {%4,%5,%6,%7}, {%8,%9}, {%0,%1,%2,%3};\n"
        : "+f"(c[0]), "+f"(c[1]), "+f"(c[2]), "+f"(c[3])
        : "r"(a[0]), "r"(a[1]), "r"(a[2]), "r"(a[3]), "r"(b[0]), "r"(b[1]));
}

// ---------------------------------------------------------------------------
// FP16 GEMM: C[M,N] = A[M,K] * B[N,K]^T (fp32 in/out, fp16 mma m16n8k16)
// 128x128 CTA tile, BK=32 (2 k16-steps), 8 warps (2x4), warp tile 64x32.
// Fragment-ordered smem; packed half2 words.
// ---------------------------------------------------------------------------
__global__ __launch_bounds__(256) void gemm_h16(const float* __restrict__ A,
                                                const float* __restrict__ Bm,
                                                float* __restrict__ C,
                                                int M, int N, int K) {
    __shared__ uint32_t Afr[2048];   // 8 m16 x 2 ik x 32 lanes x 4 regs
    __shared__ uint32_t Bfr[2048];   // 16 n8 x 2 ik x 32 lanes x 2 regs

    const int tid = threadIdx.x;
    const int lane = tid & 31, warp = tid >> 5;
    const int wm = warp >> 2, wn = warp & 3;   // 2 x 4
    const size_t bm = (size_t)blockIdx.y * 128, bn = (size_t)blockIdx.x * 128;

    const float* Abase = A + bm * K;
    const float* Bbase = Bm + bn * K;

    float4 ra[4], rb[4];
    float acc[4][4][4];
#pragma unroll
    for (int im = 0; im < 4; im++)
#pragma unroll
        for (int in = 0; in < 4; in++)
#pragma unroll
            for (int j = 0; j < 4; j++) acc[im][in][j] = 0.f;

#define LOADG(k0)                                                              \
    {                                                                          \
        _Pragma("unroll")                                                      \
        for (int s = 0; s < 4; s++) {                                          \
            int idx = tid + s * 256;                                           \
            ra[s] = *(const float4*)(Abase + (size_t)(idx >> 3) * K + (k0) + (idx & 7) * 4); \
            rb[s] = *(const float4*)(Bbase + (size_t)(idx >> 3) * K + (k0) + (idx & 7) * 4); \
        }                                                                      \
    }

#define STAGE()                                                                \
    {                                                                          \
        _Pragma("unroll")                                                      \
        for (int s = 0; s < 4; s++) {                                          \
            int idx = tid + s * 256;                                           \
            int row = idx >> 3, kq = idx & 7;                                  \
            int g = row & 7, ishi = (row >> 3) & 1, im = row >> 4;             \
            int inb = row >> 3;                                                \
            const float* pv = (const float*)&ra[s];                            \
            const float* pw = (const float*)&rb[s];                            \
            _Pragma("unroll")                                                  \
            for (int p = 0; p < 2; p++) {                                      \
                int kp = kq * 2 + p;                                           \
                int t = kp & 3, hk = (kp >> 2) & 1, ik = kp >> 3;              \
                Afr[((im * 2 + ik) * 32 + g * 4 + t) * 4 + ishi + 2 * hk] =    \
                    packh2(pv[2 * p], pv[2 * p + 1]);                          \
                Bfr[((inb * 2 + ik) * 32 + g * 4 + t) * 2 + hk] =              \
                    packh2(pw[2 * p], pw[2 * p + 1]);                          \
            }                                                                  \
        }                                                                      \
    }

    LOADG(0);
    STAGE();
    __syncthreads();

    for (int k0 = 32; k0 <= K; k0 += 32) {
        const bool more = (k0 < K);
        if (more) LOADG(k0);

#pragma unroll
        for (int ik = 0; ik < 2; ik++) {
            uint4 af[4];
            uint32_t bf[4][2];
#pragma unroll
            for (int im = 0; im < 4; im++)
                af[im] = *(const uint4*)&Afr[(((wm * 4 + im) * 2 + ik) * 32 + lane) * 4];
#pragma unroll
            for (int in = 0; in < 4; in++) {
                uint2 tt = *(const uint2*)&Bfr[(((wn * 4 + in) * 2 + ik) * 32 + lane) * 2];
                bf[in][0] = tt.x; bf[in][1] = tt.y;
            }
#pragma unroll
            for (int im = 0; im < 4; im++) {
                const uint32_t a4[4] = {af[im].x, af[im].y, af[im].z, af[im].w};
#pragma unroll
                for (int in = 0; in < 4; in++)
                    mma_f16(acc[im][in], a4, bf[in]);
            }
        }
        __syncthreads();
        if (more) {
            STAGE();
            __syncthreads();
        }
    }

#pragma unroll
    for (int im = 0; im < 4; im++) {
#pragma unroll
        for (int in = 0; in < 4; in++) {
            size_t r0 = bm + wm * 64 + im * 16 + (lane >> 2);
            size_t c0 = bn + wn * 32 + in * 8 + (lane & 3) * 2;
            *(float2*)&C[r0 * N + c0] = make_float2(acc[im][in][0], acc[im][in][1]);
            *(float2*)&C[(r0 + 8) * N + c0] = make_float2(acc[im][in][2], acc[im][in][3]);
        }
    }
#undef LOADG
#undef STAGE
}

// ---------------------------------------------------------------------------
// Fused per-head RMSNorm + RoPE (unchanged)
// ---------------------------------------------------------------------------
__global__ void norm_rope_kernel(const int* __restrict__ pos,
                                 const float* __restrict__ qw,
                                 const float* __restrict__ kw) {
    int gw = (blockIdx.x * blockDim.x + threadIdx.x) >> 5;
    int lane = threadIdx.x & 31;
    if (gw >= TOKENS * NH_NORM) return;
    int token = gw / NH_NORM;
    int h = gw - token * NH_NORM;
    int p = pos[token & (N_SEQ - 1)];

    float* ptr = g_qkv + (size_t)token * QKV_DIM + h * DHEAD;
    float x1 = ptr[lane];
    float x2 = ptr[lane + 32];
    float ss = x1 * x1 + x2 * x2;
#pragma unroll
    for (int o = 16; o; o >>= 1) ss += __shfl_xor_sync(0xffffffffu, ss, o);
    float r = rsqrtf(ss * (1.0f / 64.0f) + 1e-6f);
    const float* w = (h < HQ) ? qw : kw;
    x1 *= r * w[lane];
    x2 *= r * w[lane + 32];

    float inv = expf(-(float)(2 * lane) * (9.210340371976184f / 64.0f));
    float sv, cv;
    sincosf((float)p * inv, &sv, &cv);
    ptr[lane]      = x1 * cv - x2 * sv;
    ptr[lane + 32] = x1 * sv + x2 * cv;
}

// ---------------------------------------------------------------------------
// FP16 tensor-core causal GQA flash attention.
// Br=128 (8 warps x 16 rows), Bc=64, m16n8k16 mma, 4 k16-steps per dim.
// ---------------------------------------------------------------------------
#define ATTN_SMEM_WORDS (4096 + 2048 + 2048 + 4096)
#define ATTN_SMEM_BYTES (ATTN_SMEM_WORDS * 4)

__global__ __launch_bounds__(256) void attn_mma() {
    extern __shared__ uint32_t smu[];
    uint32_t* Qfr = smu;             // 4096: [(w*4+ik)*32 + slot]*4 + reg
    uint32_t* Kfr = smu + 4096;      // 2048: [(n*4+ik)*32 + slot]*2 + hk
    uint32_t* Vfr = smu + 6144;      // 2048: [(ik*8+dt)*32 + slot]*2 + hk
    uint32_t* Pfr = smu + 8192;      // 4096: per-warp 512

    int qb = (gridDim.x - 1) - blockIdx.x;   // big tiles first
    int h = blockIdx.y, b = blockIdx.z;
    int hk4 = h >> 2;
    int tid = threadIdx.x, lane = tid & 31, w = tid >> 5;
    int g = lane >> 2, t = lane & 3;
    size_t base = (size_t)b * N_SEQ;
    int q0 = qb * 128;

    // ---- stage Q tile (pre-scaled), fragment order + swizzle ----
#pragma unroll
    for (int s = 0; s < 8; s++) {
        int idx = tid + s * 256;
        int row = idx >> 4, f4 = idx & 15;
        float4 v = *(const float4*)&g_qkv[(base + q0 + row) * QKV_DIM + h * DHEAD + f4 * 4];
        int wq = row >> 4, ishi = (row >> 3) & 1, gq = row & 7;
        const float* pv = (const float*)&v;
#pragma unroll
        for (int p = 0; p < 2; p++) {
            int kp = f4 * 2 + p;
            int tt = kp & 3, hh = (kp >> 2) & 1, ik = kp >> 3;
            int slot = (gq * 4 + tt) ^ ((ik & 3) * 4);
            Qfr[((wq * 4 + ik) * 32 + slot) * 4 + ishi + 2 * hh] =
                packh2(pv[2 * p] * 0.125f, pv[2 * p + 1] * 0.125f);
        }
    }

    float4 rk[4], rv[4];
    const int nb = 2 * qb + 2;

#define LOADKV(kb_)                                                            \
    {                                                                          \
        int k0_ = (kb_) * 64;                                                  \
        _Pragma("unroll")                                                      \
        for (int s = 0; s < 4; s++) {                                          \
            int idx = tid + s * 256;                                           \
            int key = idx >> 4, f4 = idx & 15;                                 \
            size_t toff = (base + k0_ + key) * QKV_DIM;                        \
            rk[s] = *(const float4*)&g_qkv[toff + (HQ + hk4) * DHEAD + f4 * 4]; \
            rv[s] = *(const float4*)&g_qkv[toff + (HQ + HKV + hk4) * DHEAD + f4 * 4]; \
        }                                                                      \
    }

#define STAGEKV()                                                              \
    {                                                                          \
        __half* vh = (__half*)Vfr;                                             \
        _Pragma("unroll")                                                      \
        for (int s = 0; s < 4; s++) {                                          \
            int idx = tid + s * 256;                                           \
            int key = idx >> 4, f4 = idx & 15;                                 \
            const float* pk = (const float*)&rk[s];                            \
            const float* pw = (const float*)&rv[s];                            \
            int in = key >> 3, gb = key & 7;                                   \
            _Pragma("unroll")                                                  \
            for (int p = 0; p < 2; p++) {                                      \
                int kp = f4 * 2 + p;                                           \
                int tt = kp & 3, hh = (kp >> 2) & 1, ik = kp >> 3;             \
                int slK = (gb * 4 + tt) ^ ((ik & 3) * 4);                      \
                Kfr[((in * 4 + ik) * 32 + slK) * 2 + hh] =                     \
                    packh2(pk[2 * p], pk[2 * p + 1]);                          \
            }                                                                  \
            int tv = (key >> 1) & 3, hv = (key >> 3) & 1, ikv = key >> 4;      \
            int keylo = key & 1;                                               \
            _Pragma("unroll")                                                  \
            for (int e = 0; e < 4; e++) {                                      \
                int d = f4 * 4 + e;                                            \
                int dt = d >> 3, gv = d & 7;                                   \
                int slV = (gv * 4 + tv) ^ ((dt & 3) * 4);                      \
                int hidx = ((((ikv * 8 + dt) * 32 + slV) * 2 + hv) << 1) | keylo; \
                vh[hidx] = __float2half(pw[e]);                                \
            }                                                                  \
        }                                                                      \
    }

    float m0 = -CUDART_INF_F, m1 = -CUDART_INF_F, l0 = 0.f, l1 = 0.f;
    float o[8][4];
#pragma unroll
    for (int dt = 0; dt < 8; dt++)
#pragma unroll
        for (int j = 0; j < 4; j++) o[dt][j] = 0.f;

    uint32_t* Pw = Pfr + w * 512;
    const int row0 = q0 + w * 16 + g;

    LOADKV(0);

    for (int kb = 0; kb < nb; kb++) {
        if (kb > 0) __syncthreads();
        STAGEKV();
        __syncthreads();
        if (kb + 1 < nb) LOADKV(kb + 1);

        // ---- S = Q K^T ----
        float sacc[8][4];
#pragma unroll
        for (int n = 0; n < 8; n++)
#pragma unroll
            for (int j = 0; j < 4; j++) sacc[n][j] = 0.f;

#pragma unroll
        for (int ik = 0; ik < 4; ik++) {
            uint4 aq = *(const uint4*)&Qfr[((w * 4 + ik) * 32 + (lane ^ ((ik & 3) * 4))) * 4];
            const uint32_t a4[4] = {aq.x, aq.y, aq.z, aq.w};
#pragma unroll
            for (int n = 0; n < 8; n++) {
                uint2 bk = *(const uint2*)&Kfr[((n * 4 + ik) * 32 + (lane ^ ((ik & 3) * 4))) * 2];
                const uint32_t b2[2] = {bk.x, bk.y};
                mma_f16(sacc[n], a4, b2);
            }
        }

        // ---- causal mask ----
        if (kb >= 2 * qb) {
            int k0 = kb * 64;
#pragma unroll
            for (int n = 0; n < 8; n++) {
                int cb = k0 + n * 8 + 2 * t;
                if (cb > row0)     sacc[n][0] = -1e30f;
                if (cb + 1 > row0) sacc[n][1] = -1e30f;
                if (cb > row0 + 8)     sacc[n][2] = -1e30f;
                if (cb + 1 > row0 + 8) sacc[n][3] = -1e30f;
            }
        }

        // ---- online softmax ----
        float mx0 = -1e30f, mx1 = -1e30f;
#pragma unroll
        for (int n = 0; n < 8; n++) {
            mx0 = fmaxf(mx0, fmaxf(sacc[n][0], sacc[n][1]));
            mx1 = fmaxf(mx1, fmaxf(sacc[n][2], sacc[n][3]));
        }
        mx0 = fmaxf(mx0, __shfl_xor_sync(0xffffffffu, mx0, 1));
        mx0 = fmaxf(mx0, __shfl_xor_sync(0xffffffffu, mx0, 2));
        mx1 = fmaxf(mx1, __shfl_xor_sync(0xffffffffu, mx1, 1));
        mx1 = fmaxf(mx1, __shfl_xor_sync(0xffffffffu, mx1, 2));

        float mn0 = fmaxf(m0, mx0), mn1 = fmaxf(m1, mx1);
        float c0 = __expf(m0 - mn0), c1 = __expf(m1 - mn1);
        float s0 = 0.f, s1 = 0.f;
#pragma unroll
        for (int n = 0; n < 8; n++) {
            sacc[n][0] = __expf(sacc[n][0] - mn0);
            sacc[n][1] = __expf(sacc[n][1] - mn0);
            sacc[n][2] = __expf(sacc[n][2] - mn1);
            sacc[n][3] = __expf(sacc[n][3] - mn1);
            s0 += sacc[n][0] + sacc[n][1];
            s1 += sacc[n][2] + sacc[n][3];
        }
        s0 += __shfl_xor_sync(0xffffffffu, s0, 1);
        s0 += __shfl_xor_sync(0xffffffffu, s0, 2);
        s1 += __shfl_xor_sync(0xffffffffu, s1, 1);
        s1 += __shfl_xor_sync(0xffffffffu, s1, 2);
        l0 = l0 * c0 + s0; l1 = l1 * c1 + s1;
        m0 = mn0; m1 = mn1;
#pragma unroll
        for (int dt = 0; dt < 8; dt++) {
            o[dt][0] *= c0; o[dt][1] *= c0;
            o[dt][2] *= c1; o[dt][3] *= c1;
        }

        // ---- write P as fp16 A-fragments (packs directly from reg pairs) ----
#pragma unroll
        for (int n = 0; n < 8; n++) {
            int ikp = n >> 1, hkp = n & 1;
            Pw[(ikp * 32 + g * 4 + t) * 4 + 0 + 2 * hkp] = packh2(sacc[n][0], sacc[n][1]);
            Pw[(ikp * 32 + g * 4 + t) * 4 + 1 + 2 * hkp] = packh2(sacc[n][2], sacc[n][3]);
        }
        __syncwarp();

        // ---- O += P V ----
#pragma unroll
        for (int ik = 0; ik < 4; ik++) {
            uint4 ap = *(const uint4*)&Pw[(ik * 32 + lane) * 4];
            const uint32_t a4[4] = {ap.x, ap.y, ap.z, ap.w};
#pragma unroll
            for (int dt = 0; dt < 8; dt++) {
                uint2 bv = *(const uint2*)&Vfr[((ik * 8 + dt) * 32 + (lane ^ ((dt & 3) * 4))) * 2];
                const uint32_t b2[2] = {bv.x, bv.y};
                mma_f16(o[dt], a4, b2);
            }
        }
    }

    // ---- epilogue ----
    float i0 = 1.f / l0, i1 = 1.f / l1;
#pragma unroll
    for (int dt = 0; dt < 8; dt++) {
        int col = h * DHEAD + dt * 8 + 2 * t;
        *(float2*)&g_y[(base + row0) * DMODEL + col] = make_float2(o[dt][0] * i0, o[dt][1] * i0);
        *(float2*)&g_y[(base + row0 + 8) * DMODEL + col] = make_float2(o[dt][2] * i1, o[dt][3] * i1);
    }
#undef LOADKV
#undef STAGEKV
}

// ---------------------------------------------------------------------------
// Launch
// ---------------------------------------------------------------------------
extern "C" void kernel_launch(void* const* d_in, const int* in_sizes, int n_in,
                              void* d_out, int out_size) {
    const float* x     = (const float*)d_in[0];
    const int*   pos   = (const int*)d_in[2];
    const float* qkv_w = (const float*)d_in[3];
    const float* out_w = (const float*)d_in[4];
    const float* qnw   = (const float*)d_in[5];
    const float* knw   = (const float*)d_in[6];
    float* out = (float*)d_out;

    float *qkv_buf, *y_buf;
    cudaGetSymbolAddress((void**)&qkv_buf, g_qkv);
    cudaGetSymbolAddress((void**)&y_buf, g_y);

    gemm_h16<<<dim3(QKV_DIM / 128, TOKENS / 128), 256>>>(x, qkv_w, qkv_buf,
                                                         TOKENS, QKV_DIM, DMODEL);
    {
        int warps = TOKENS * NH_NORM;
        int threads = warps * 32;
        norm_rope_kernel<<<(threads + 255) / 256, 256>>>(pos, qnw, knw);
    }
    cudaFuncSetAttribute(attn_mma, cudaFuncAttributeMaxDynamicSharedMemorySize,
                         ATTN_SMEM_BYTES);
    attn_mma<<<dim3(N_SEQ / 128, HQ, B_SZ), 256, ATTN_SMEM_BYTES>>>();
    gemm_h16<<<dim3(DMODEL / 128, TOKENS / 128), 256>>>(y_buf, out_w, out,
                                                        TOKENS, DMODEL, DMODEL);
}